// round 3
// baseline (speedup 1.0000x reference)
#include <cuda_runtime.h>
#include <cstdint>

typedef unsigned long long u64;

__device__ __forceinline__ u64 pack2(float a, float b) {
    u64 r; asm("mov.b64 %0, {%1, %2};" : "=l"(r) : "f"(a), "f"(b)); return r;
}
__device__ __forceinline__ void fma2(u64& acc, u64 x, u64 w) {
    asm("fma.rn.f32x2 %0, %1, %2, %0;" : "+l"(acc) : "l"(x), "l"(w));
}
__device__ __forceinline__ float2 unpack2(u64 v) {
    float2 f; asm("mov.b64 {%0, %1}, %2;" : "=f"(f.x), "=f"(f.y) : "l"(v)); return f;
}

// Static multi-resolution layout
//   levels R = 16, 32, 48, 64 ; level base offsets in N: 0, 4096, 36864, 147456
//   N_TOTAL = 409600, B = 4, Cin = Cout = 16, K = 3
// Tiling: 8x8x8 outputs per block; 256 threads.
// Thread (lx, ly, h, zg): z-column of 4 voxels (z0 + 4*zg ..), couts h*8..h*8+7.
// h is tid bit 6 -> constant within a warp, so weight LDS stays broadcast.
// Smem x tile: [cg(4)][hz(10)][hy(10)][hx(10)] of float4 (conflict-free LDS.128).
constexpr int N_TOTAL  = 409600;
constexpr int WS_FLOATS = 27 * 16 * 16;            // 6912: [tap][cin][cout]
constexpr int XS_F4     = 4 * 1000;                // 4 channel-groups x 10^3 rows
constexpr size_t SMEM_BYTES = (size_t)WS_FLOATS * 4 + (size_t)XS_F4 * 16; // 91648 B

__global__ __launch_bounds__(256, 2)
void conv3d_ml_kernel(const float* __restrict__ in, const float* __restrict__ wgt,
                      const float* __restrict__ bias, float* __restrict__ out)
{
    extern __shared__ __align__(16) float smem[];
    float*  ws  = smem;                          // [27][16][16]
    float4* xs4 = (float4*)(smem + WS_FLOATS);   // [cg][hz][hy][hx]

    const int t = threadIdx.x;

    // ---- stage weights: reorder [cout][cin][tap] -> [tap][cin][cout] ----
    for (int i = t; i < WS_FLOATS; i += 256) {
        int cout = i & 15, cin = (i >> 4) & 15, tap = i >> 8;
        ws[i] = wgt[(cout * 16 + cin) * 27 + tap];
    }

    // ---- decode block -> (batch, level, tile coords) ----
    int bid = blockIdx.x;
    int b = bid / 800;
    int tl = bid - b * 800;
    int R, nbase, lt;
    if (tl < 8)        { R = 16; nbase = 0;      lt = tl;       }
    else if (tl < 72)  { R = 32; nbase = 4096;   lt = tl - 8;   }
    else if (tl < 288) { R = 48; nbase = 36864;  lt = tl - 72;  }
    else               { R = 64; nbase = 147456; lt = tl - 288; }
    const int td = R >> 3;
    const int tx = lt % td; const int tmp = lt / td;
    const int ty = tmp % td; const int tz = tmp / td;
    const int x0 = tx << 3, y0 = ty << 3, z0 = tz << 3;

    const float* inb = in + ((size_t)b * N_TOTAL + nbase) * 16;

    // ---- stage halo tile 10x10x10 x 16ch into cg-major float4 layout ----
    for (int i = t; i < 4000; i += 256) {
        int comp = i & 3;
        int row  = i >> 2;
        int hx = row % 10; int r2 = row / 10; int hy = r2 % 10; int hz = r2 / 10;
        int gx = x0 + hx - 1, gy = y0 + hy - 1, gz = z0 + hz - 1;
        float4 v = make_float4(0.f, 0.f, 0.f, 0.f);
        if ((unsigned)gx < (unsigned)R && (unsigned)gy < (unsigned)R && (unsigned)gz < (unsigned)R) {
            v = *(const float4*)(inb + (size_t)((gz * R + gy) * R + gx) * 16 + comp * 4);
        }
        xs4[comp * 1000 + row] = v;
    }
    __syncthreads();

    // ---- compute: thread owns (lx, ly, z col of 4), 8 couts (half h) ----
    const int lx = t & 7, ly = (t >> 3) & 7;
    const int h  = (t >> 6) & 1;          // cout half: warp-uniform
    const int lz = (t >> 7) << 2;         // z-group

    u64 acc[4][4];   // [voxel][cout-pair within half]
    #pragma unroll
    for (int v = 0; v < 4; ++v)
        #pragma unroll
        for (int p = 0; p < 4; ++p) acc[v][p] = 0ull;

    #pragma unroll 1
    for (int dy = 0; dy < 3; ++dy) {
        #pragma unroll 1
        for (int dx = 0; dx < 3; ++dx) {
            const int sb = (ly + dy) * 10 + (lx + dx);   // row index w/o hz, cg
            #pragma unroll 1
            for (int q = 0; q < 4; ++q) {                // channel group: cin = 4q..4q+3
                // 6 z-slices of this channel group, pre-duplicated for f32x2
                u64 xp[6][4];
                #pragma unroll
                for (int s = 0; s < 6; ++s) {
                    float4 v = xs4[q * 1000 + (lz + s) * 100 + sb];
                    xp[s][0] = pack2(v.x, v.x);
                    xp[s][1] = pack2(v.y, v.y);
                    xp[s][2] = pack2(v.z, v.z);
                    xp[s][3] = pack2(v.w, v.w);
                }
                #pragma unroll
                for (int dz = 0; dz < 3; ++dz) {
                    const float* wt = ws + ((dz * 3 + dy) * 3 + dx) * 256 + h * 8;
                    #pragma unroll
                    for (int c = 0; c < 4; ++c) {
                        const ulonglong2* wp = (const ulonglong2*)(wt + (q * 4 + c) * 16);
                        ulonglong2 w01 = wp[0];   // couts h*8 .. h*8+3
                        ulonglong2 w23 = wp[1];   // couts h*8+4 .. h*8+7
                        #pragma unroll
                        for (int v = 0; v < 4; ++v) {
                            u64 xx = xp[dz + v][c];
                            fma2(acc[v][0], xx, w01.x);
                            fma2(acc[v][1], xx, w01.y);
                            fma2(acc[v][2], xx, w23.x);
                            fma2(acc[v][3], xx, w23.y);
                        }
                    }
                }
            }
        }
    }

    // ---- epilogue: + bias, store 8 couts per voxel as 2 float4s ----
    const float4* b4 = (const float4*)bias;
    const float4 bb0 = b4[h * 2 + 0], bb1 = b4[h * 2 + 1];

    #pragma unroll
    for (int v = 0; v < 4; ++v) {
        const int gz = z0 + lz + v, gy = y0 + ly, gx = x0 + lx;
        const size_t n = (size_t)nbase + (size_t)(gz * R + gy) * R + gx;
        float* o = out + ((size_t)b * N_TOTAL + n) * 16 + h * 8;

        float2 q0 = unpack2(acc[v][0]), q1 = unpack2(acc[v][1]);
        float2 q2 = unpack2(acc[v][2]), q3 = unpack2(acc[v][3]);

        *(float4*)(o + 0) = make_float4(q0.x + bb0.x, q0.y + bb0.y, q1.x + bb0.z, q1.y + bb0.w);
        *(float4*)(o + 4) = make_float4(q2.x + bb1.x, q2.y + bb1.y, q3.x + bb1.z, q3.y + bb1.w);
    }
}

extern "C" void kernel_launch(void* const* d_in, const int* in_sizes, int n_in,
                              void* d_out, int out_size) {
    (void)in_sizes; (void)n_in; (void)out_size;
    const float* in  = (const float*)d_in[0];
    const float* w   = (const float*)d_in[1];
    const float* bs  = (const float*)d_in[2];
    float* out = (float*)d_out;

    cudaFuncSetAttribute(conv3d_ml_kernel,
                         cudaFuncAttributeMaxDynamicSharedMemorySize, (int)SMEM_BYTES);
    conv3d_ml_kernel<<<3200, 256, SMEM_BYTES>>>(in, w, bs, out);
}

// round 5
// speedup vs baseline: 1.3289x; 1.3289x over previous
#include <cuda_runtime.h>
#include <cstdint>

// Round 5: warp-level tf32 mma.sync implicit-GEMM (tcgen05 is sm_103a-gated and
// the harness targets sm_103 baseline PTX, so legacy HMMA path is used).
//
// Per block: tile = 128 voxels (2z x 8y x 8x) x 16 couts, K = 27 taps * 16 cin.
// 8 warps, warp w owns voxel rows m = 16w .. 16w+15.
// D += A(voxels x k) * B(k x couts) via mma.m16n8k8.tf32, 54 k-steps, 2 n-tiles.
//
// Smem: halo rows stride 20 floats  -> A-fragment LDS conflict-free
//       weights cout stride 12 floats -> B-fragment LDS conflict-free
// Activations and weights rounded to tf32 (cvt.rna) at staging time.

constexpr int N_TOTAL = 409600;

constexpr int W_KSTEP_F = 16 * 12;          // floats per k-step: 16 couts x stride12
constexpr int W_FLOATS  = 54 * W_KSTEP_F;   // 10368
constexpr int HALO_ROW_F = 20;              // 16 ch + 4 pad
constexpr int HALO_ROWS  = 4 * 10 * 10;     // hz 0..3, hy 0..9, hx 0..9
constexpr int HALO_FLOATS = HALO_ROWS * HALO_ROW_F;  // 8000
constexpr size_t SMEM_BYTES = (size_t)(W_FLOATS + HALO_FLOATS) * 4;  // 73472

__device__ __forceinline__ uint32_t cvt_tf32(float v) {
    uint32_t o; asm("cvt.rna.tf32.f32 %0, %1;" : "=r"(o) : "f"(v)); return o;
}

__device__ __forceinline__ void mma_tf32(float c[4], uint32_t a0, uint32_t a1,
                                         uint32_t a2, uint32_t a3,
                                         uint32_t b0, uint32_t b1) {
    asm volatile("mma.sync.aligned.m16n8k8.row.col.f32.tf32.tf32.f32 "
                 "{%0,%1,%2,%3}, {%4,%5,%6,%7}, {%8,%9}, {%0,%1,%2,%3};"
                 : "+f"(c[0]), "+f"(c[1]), "+f"(c[2]), "+f"(c[3])
                 : "r"(a0), "r"(a1), "r"(a2), "r"(a3), "r"(b0), "r"(b1));
}

__global__ __launch_bounds__(256)
void conv3d_mma_kernel(const float* __restrict__ in, const float* __restrict__ wgt,
                       const float* __restrict__ bias, float* __restrict__ out)
{
    extern __shared__ __align__(16) float smem[];
    float* ws   = smem;              // [kstep 54][cout 16 (stride 12)][cin 8]
    float* halo = smem + W_FLOATS;   // [row 400][20]  (ch 0..15 + pad)

    const int t = threadIdx.x;
    const int wid = t >> 5, lane = t & 31;

    // ---- decode block -> (batch, level, tile) ----
    int bid = blockIdx.x;
    int b = bid / 3200;
    int tl = bid - b * 3200;
    int R, nbase, lt;
    if (tl < 32)        { R = 16; nbase = 0;      lt = tl;        }
    else if (tl < 288)  { R = 32; nbase = 4096;   lt = tl - 32;   }
    else if (tl < 1152) { R = 48; nbase = 36864;  lt = tl - 288;  }
    else                { R = 64; nbase = 147456; lt = tl - 1152; }
    const int td = R >> 3;
    const int tx = lt % td; const int t2 = lt / td;
    const int ty = t2 % td; const int tz = t2 / td;
    const int x0 = tx << 3, y0 = ty << 3, z0 = tz << 1;

    // ---- stage weights (rna -> tf32): ws[kstep][cout*12 + cin'] ----
    for (int i = t; i < 6912; i += 256) {
        int kstep = i >> 7;
        int r = i & 127;
        int cout = r >> 3, cin = r & 7;
        int tap = kstep >> 1;
        int ci  = ((kstep & 1) << 3) | cin;
        float w = wgt[(cout * 16 + ci) * 27 + tap];
        ws[kstep * W_KSTEP_F + cout * 12 + cin] = __uint_as_float(cvt_tf32(w));
    }

    // ---- stage halo (rna -> tf32), row stride 20 floats ----
    const float* inb = in + ((size_t)b * N_TOTAL + nbase) * 16;
    for (int i = t; i < 1600; i += 256) {
        int c = i & 3, row = i >> 2;
        int hx = row % 10; int r2 = row / 10; int hy = r2 % 10; int hz = r2 / 10;
        int gx = x0 + hx - 1, gy = y0 + hy - 1, gz = z0 + hz - 1;
        float4 v = make_float4(0.f, 0.f, 0.f, 0.f);
        if ((unsigned)gx < (unsigned)R && (unsigned)gy < (unsigned)R && (unsigned)gz < (unsigned)R)
            v = *(const float4*)(inb + (size_t)((gz * R + gy) * R + gx) * 16 + c * 4);
        float4 o;
        o.x = __uint_as_float(cvt_tf32(v.x));
        o.y = __uint_as_float(cvt_tf32(v.y));
        o.z = __uint_as_float(cvt_tf32(v.z));
        o.w = __uint_as_float(cvt_tf32(v.w));
        *(float4*)(halo + row * HALO_ROW_F + c * 4) = o;
    }
    __syncthreads();

    // ---- per-thread fragment coordinates ----
    const int r4 = lane >> 2;          // 0..7
    const int c4 = lane & 3;           // 0..3
    const int m_lo = wid * 16 + r4;    // voxel rows of a0/a2
    const int m_hi = m_lo + 8;         // voxel rows of a1/a3
    const int lz   = wid >> 2;         // same for lo/hi
    const int ly_lo = (m_lo >> 3) & 7, lx_lo = m_lo & 7;
    const int ly_hi = (m_hi >> 3) & 7, lx_hi = m_hi & 7;
    const int base_lo = (lz * 10 + ly_lo) * 10 + lx_lo;
    const int base_hi = (lz * 10 + ly_hi) * 10 + lx_hi;
    const int g12 = r4 * 12;           // B-fragment cout offset

    float ca[4] = {0.f, 0.f, 0.f, 0.f};   // couts 0..7
    float cb[4] = {0.f, 0.f, 0.f, 0.f};   // couts 8..15

    const float* wk = ws + g12 + c4;

    #pragma unroll 1
    for (int dz = 0; dz < 3; ++dz) {
        #pragma unroll 1
        for (int dy = 0; dy < 3; ++dy) {
            #pragma unroll 1
            for (int dx = 0; dx < 3; ++dx) {
                const int off = dz * 100 + dy * 10 + dx;
                const float* hlo = halo + (base_lo + off) * HALO_ROW_F + c4;
                const float* hhi = halo + (base_hi + off) * HALO_ROW_F + c4;
                #pragma unroll
                for (int h = 0; h < 2; ++h) {
                    uint32_t a0 = __float_as_uint(hlo[8 * h]);
                    uint32_t a1 = __float_as_uint(hhi[8 * h]);
                    uint32_t a2 = __float_as_uint(hlo[8 * h + 4]);
                    uint32_t a3 = __float_as_uint(hhi[8 * h + 4]);
                    const float* wp = wk + h * W_KSTEP_F;
                    uint32_t b0 = __float_as_uint(wp[0]);
                    uint32_t b1 = __float_as_uint(wp[4]);
                    mma_tf32(ca, a0, a1, a2, a3, b0, b1);
                    uint32_t b0h = __float_as_uint(wp[96]);
                    uint32_t b1h = __float_as_uint(wp[100]);
                    mma_tf32(cb, a0, a1, a2, a3, b0h, b1h);
                }
                wk += 2 * W_KSTEP_F;
            }
        }
    }

    // ---- epilogue: +bias, store. c0/c1 -> row m_lo, c2/c3 -> row m_hi ----
    const int n0 = 2 * c4;
    const float bl0 = bias[n0],     bl1 = bias[n0 + 1];
    const float bh0 = bias[8 + n0], bh1 = bias[8 + n0 + 1];

    {
        const int gz = z0 + lz, gy = y0 + ly_lo, gx = x0 + lx_lo;
        float* o = out + ((size_t)b * N_TOTAL + nbase +
                          (size_t)((gz * R + gy) * R + gx)) * 16;
        *(float2*)(o + n0)     = make_float2(ca[0] + bl0, ca[1] + bl1);
        *(float2*)(o + 8 + n0) = make_float2(cb[0] + bh0, cb[1] + bh1);
    }
    {
        const int gz = z0 + lz, gy = y0 + ly_hi, gx = x0 + lx_hi;
        float* o = out + ((size_t)b * N_TOTAL + nbase +
                          (size_t)((gz * R + gy) * R + gx)) * 16;
        *(float2*)(o + n0)     = make_float2(ca[2] + bl0, ca[3] + bl1);
        *(float2*)(o + 8 + n0) = make_float2(cb[2] + bh0, cb[3] + bh1);
    }
}

extern "C" void kernel_launch(void* const* d_in, const int* in_sizes, int n_in,
                              void* d_out, int out_size) {
    (void)in_sizes; (void)n_in; (void)out_size;
    const float* in  = (const float*)d_in[0];
    const float* w   = (const float*)d_in[1];
    const float* bs  = (const float*)d_in[2];
    float* out = (float*)d_out;

    cudaFuncSetAttribute(conv3d_mma_kernel,
                         cudaFuncAttributeMaxDynamicSharedMemorySize, (int)SMEM_BYTES);
    conv3d_mma_kernel<<<12800, 256, SMEM_BYTES>>>(in, w, bs, out);
}

// round 6
// speedup vs baseline: 1.8519x; 1.3936x over previous
#include <cuda_runtime.h>
#include <cstdint>

// Round 6: tf32 mma.sync implicit-GEMM, vectorized LDS.128 via channel
// permutation, 256-voxel tiles (4z x 8y x 8x), 4 warps (one z-slab each,
// 4 m16-subtiles) so B-fragment loads amortize 4x.
//
// Smem channel permutation: pos(ch) = (ch%4)*4 + ch/4. Thread c4 = lane&3
// reads positions 4*c4..4*c4+3 = channels {c4, c4+4, c4+8, c4+12} = exactly
// its A/B fragment values for BOTH k-steps of a tap -> one LDS.128.
// Row stride 16 floats -> quad index (4*r4 + c4) mod 8: conflict-free.

constexpr int N_TOTAL = 409600;

constexpr int W_FLOATS   = 27 * 16 * 16;        // [tap][cout][pos], stride 16
constexpr int HALO_ROWS  = 6 * 10 * 10;         // hz 0..5, hy 0..9, hx 0..9
constexpr int HALO_FLOATS = HALO_ROWS * 16;     // 9600
constexpr size_t SMEM_BYTES = (size_t)(W_FLOATS + HALO_FLOATS) * 4;  // 66048

__device__ __forceinline__ float cvt_tf32(float v) {
    uint32_t o; asm("cvt.rna.tf32.f32 %0, %1;" : "=r"(o) : "f"(v));
    return __uint_as_float(o);
}

__device__ __forceinline__ void mma_tf32(float c[4], float a0f, float a1f,
                                         float a2f, float a3f,
                                         float b0f, float b1f) {
    uint32_t a0 = __float_as_uint(a0f), a1 = __float_as_uint(a1f);
    uint32_t a2 = __float_as_uint(a2f), a3 = __float_as_uint(a3f);
    uint32_t b0 = __float_as_uint(b0f), b1 = __float_as_uint(b1f);
    asm volatile("mma.sync.aligned.m16n8k8.row.col.f32.tf32.tf32.f32 "
                 "{%0,%1,%2,%3}, {%4,%5,%6,%7}, {%8,%9}, {%0,%1,%2,%3};"
                 : "+f"(c[0]), "+f"(c[1]), "+f"(c[2]), "+f"(c[3])
                 : "r"(a0), "r"(a1), "r"(a2), "r"(a3), "r"(b0), "r"(b1));
}

__global__ __launch_bounds__(128)
void conv3d_mma_kernel(const float* __restrict__ in, const float* __restrict__ wgt,
                       const float* __restrict__ bias, float* __restrict__ out)
{
    extern __shared__ __align__(16) float smem[];
    float* ws   = smem;               // [tap 27][cout 16][pos 16]
    float* halo = smem + W_FLOATS;    // [row 600][pos 16]

    const int t = threadIdx.x;
    const int wid = t >> 5, lane = t & 31;
    const int r4 = lane >> 2, c4 = lane & 3;

    // ---- decode block -> (batch, level, tile). 256-voxel tiles. ----
    // tiles/batch: R16:16, R32:128, R48:432, R64:1024 -> 1600; grid = 6400.
    int bid = blockIdx.x;
    int b = bid / 1600;
    int tl = bid - b * 1600;
    int R, nbase, lt;
    if (tl < 16)       { R = 16; nbase = 0;      lt = tl;       }
    else if (tl < 144) { R = 32; nbase = 4096;   lt = tl - 16;  }
    else if (tl < 576) { R = 48; nbase = 36864;  lt = tl - 144; }
    else               { R = 64; nbase = 147456; lt = tl - 576; }
    const int td = R >> 3;
    const int tx = lt % td; const int t2 = lt / td;
    const int ty = t2 % td; const int tz = t2 / td;
    const int x0 = tx << 3, y0 = ty << 3, z0 = tz << 2;

    // ---- stage weights: ws[tap][cout][pos(ch)] (rna -> tf32) ----
    for (int i = t; i < 6912; i += 128) {
        int tap = i >> 8;
        int rem = i & 255;
        int cout = rem >> 4, ch = rem & 15;
        int pos = ((ch & 3) << 2) | (ch >> 2);
        ws[tap * 256 + cout * 16 + pos] =
            cvt_tf32(wgt[(cout * 16 + ch) * 27 + tap]);
    }

    // ---- stage halo: 600 rows x 16ch, permuted, j-rotated stores ----
    const float* inb = in + ((size_t)b * N_TOTAL + nbase) * 16;
    for (int row = t; row < 600; row += 128) {
        int hx = row % 10; int r2 = row / 10; int hy = r2 % 10; int hz = r2 / 10;
        int gx = x0 + hx - 1, gy = y0 + hy - 1, gz = z0 + hz - 1;
        float4 v0, v1, v2, v3;
        if ((unsigned)gx < (unsigned)R && (unsigned)gy < (unsigned)R && (unsigned)gz < (unsigned)R) {
            const float4* g = (const float4*)(inb + (size_t)((gz * R + gy) * R + gx) * 16);
            v0 = g[0]; v1 = g[1]; v2 = g[2]; v3 = g[3];
        } else {
            v0 = v1 = v2 = v3 = make_float4(0.f, 0.f, 0.f, 0.f);
        }
        float c[4][4] = {
            {v0.x, v1.x, v2.x, v3.x},   // quad 0: ch 0,4,8,12
            {v0.y, v1.y, v2.y, v3.y},   // quad 1: ch 1,5,9,13
            {v0.z, v1.z, v2.z, v3.z},
            {v0.w, v1.w, v2.w, v3.w},
        };
        float4* hrow = (float4*)(halo + row * 16);
        #pragma unroll
        for (int jj = 0; jj < 4; ++jj) {
            int j = (jj + row) & 3;   // rotate store order: lowers STS conflicts
            hrow[j] = make_float4(cvt_tf32(c[j][0]), cvt_tf32(c[j][1]),
                                  cvt_tf32(c[j][2]), cvt_tf32(c[j][3]));
        }
    }
    __syncthreads();

    // ---- compute: warp wid = z-slab lz = wid; 4 m16-subtiles (ly pairs) ----
    float acc[4][2][4];
    #pragma unroll
    for (int s = 0; s < 4; ++s)
        #pragma unroll
        for (int n = 0; n < 2; ++n)
            #pragma unroll
            for (int k = 0; k < 4; ++k) acc[s][n][k] = 0.f;

    const float4* hq = (const float4*)halo;   // row*4 + quad
    const float4* wq = (const float4*)ws;     // tap*64 + cout*4 + quad

    #pragma unroll 1
    for (int dz = 0; dz < 3; ++dz) {
        #pragma unroll 1
        for (int dy = 0; dy < 3; ++dy) {
            #pragma unroll 1
            for (int dx = 0; dx < 3; ++dx) {
                const int tap = (dz * 3 + dy) * 3 + dx;
                float4 bl = wq[tap * 64 + r4 * 4 + c4];         // couts r4
                float4 bh = wq[tap * 64 + (r4 + 8) * 4 + c4];   // couts r4+8
                const int base = ((wid + dz) * 10 + dy) * 10 + (r4 + dx);
                #pragma unroll
                for (int s = 0; s < 4; ++s) {
                    float4 lo = hq[(base + 20 * s) * 4 + c4];        // ly = 2s+dy
                    float4 hi = hq[(base + 20 * s + 10) * 4 + c4];   // ly = 2s+1+dy
                    mma_tf32(acc[s][0], lo.x, hi.x, lo.y, hi.y, bl.x, bl.y);
                    mma_tf32(acc[s][1], lo.x, hi.x, lo.y, hi.y, bh.x, bh.y);
                    mma_tf32(acc[s][0], lo.z, hi.z, lo.w, hi.w, bl.z, bl.w);
                    mma_tf32(acc[s][1], lo.z, hi.z, lo.w, hi.w, bh.z, bh.w);
                }
            }
        }
    }

    // ---- epilogue: +bias, store ----
    const int n0 = 2 * c4;
    const float bl0 = bias[n0],     bl1 = bias[n0 + 1];
    const float bh0 = bias[8 + n0], bh1 = bias[8 + n0 + 1];

    const int gz = z0 + wid, gx = x0 + r4;
    #pragma unroll
    for (int s = 0; s < 4; ++s) {
        const int gy_lo = y0 + 2 * s, gy_hi = gy_lo + 1;
        float* olo = out + ((size_t)b * N_TOTAL + nbase +
                            (size_t)((gz * R + gy_lo) * R + gx)) * 16;
        float* ohi = out + ((size_t)b * N_TOTAL + nbase +
                            (size_t)((gz * R + gy_hi) * R + gx)) * 16;
        *(float2*)(olo + n0)     = make_float2(acc[s][0][0] + bl0, acc[s][0][1] + bl1);
        *(float2*)(olo + 8 + n0) = make_float2(acc[s][1][0] + bh0, acc[s][1][1] + bh1);
        *(float2*)(ohi + n0)     = make_float2(acc[s][0][2] + bl0, acc[s][0][3] + bl1);
        *(float2*)(ohi + 8 + n0) = make_float2(acc[s][1][2] + bh0, acc[s][1][3] + bh1);
    }
}

extern "C" void kernel_launch(void* const* d_in, const int* in_sizes, int n_in,
                              void* d_out, int out_size) {
    (void)in_sizes; (void)n_in; (void)out_size;
    const float* in  = (const float*)d_in[0];
    const float* w   = (const float*)d_in[1];
    const float* bs  = (const float*)d_in[2];
    float* out = (float*)d_out;

    cudaFuncSetAttribute(conv3d_mma_kernel,
                         cudaFuncAttributeMaxDynamicSharedMemorySize, (int)SMEM_BYTES);
    conv3d_mma_kernel<<<6400, 128, SMEM_BYTES>>>(in, w, bs, out);
}

// round 8
// speedup vs baseline: 2.6367x; 1.4237x over previous
#include <cuda_runtime.h>
#include <cstdint>

// Round 8: Round 7 with the weight-staging copy bound fixed (1728 float4
// needs 14 strides of 128, not 13 — taps 23..26 were garbage).
//  - weights pre-transposed + tf32-rounded ONCE by a prep kernel into d_ws.
//  - A-fragment rows register-cached across the dy loop (10-row window).
//  - tile = 256 voxels (4z x 8y x 8x), 4 warps (one z-slab each).

constexpr int N_TOTAL = 409600;

constexpr int W_FLOATS   = 27 * 16 * 16;        // 6912
constexpr int HALO_ROWS  = 6 * 10 * 10;
constexpr int HALO_FLOATS = HALO_ROWS * 16;     // 9600
constexpr size_t SMEM_BYTES = (size_t)(W_FLOATS + HALO_FLOATS) * 4;  // 66048

__device__ float d_ws[W_FLOATS];   // [tap][cout][pos], tf32-rounded

__device__ __forceinline__ float cvt_tf32(float v) {
    uint32_t o; asm("cvt.rna.tf32.f32 %0, %1;" : "=r"(o) : "f"(v));
    return __uint_as_float(o);
}

__device__ __forceinline__ void mma_tf32(float c[4], float a0f, float a1f,
                                         float a2f, float a3f,
                                         float b0f, float b1f) {
    uint32_t a0 = __float_as_uint(a0f), a1 = __float_as_uint(a1f);
    uint32_t a2 = __float_as_uint(a2f), a3 = __float_as_uint(a3f);
    uint32_t b0 = __float_as_uint(b0f), b1 = __float_as_uint(b1f);
    asm volatile("mma.sync.aligned.m16n8k8.row.col.f32.tf32.tf32.f32 "
                 "{%0,%1,%2,%3}, {%4,%5,%6,%7}, {%8,%9}, {%0,%1,%2,%3};"
                 : "+f"(c[0]), "+f"(c[1]), "+f"(c[2]), "+f"(c[3])
                 : "r"(a0), "r"(a1), "r"(a2), "r"(a3), "r"(b0), "r"(b1));
}

// ---- prep: transpose + round weights once per launch ----
__global__ void weight_prep_kernel(const float* __restrict__ wgt) {
    int i = blockIdx.x * 256 + threadIdx.x;
    if (i >= W_FLOATS) return;
    int tap = i >> 8;
    int rem = i & 255;
    int cout = rem >> 4, ch = rem & 15;
    int pos = ((ch & 3) << 2) | (ch >> 2);
    d_ws[tap * 256 + cout * 16 + pos] = cvt_tf32(wgt[(cout * 16 + ch) * 27 + tap]);
}

__global__ __launch_bounds__(128)
void conv3d_mma_kernel(const float* __restrict__ in,
                       const float* __restrict__ bias, float* __restrict__ out)
{
    extern __shared__ __align__(16) float smem[];
    float* ws   = smem;               // [tap 27][cout 16][pos 16]
    float* halo = smem + W_FLOATS;    // [row 600][pos 16]

    const int t = threadIdx.x;
    const int wid = t >> 5, lane = t & 31;
    const int r4 = lane >> 2, c4 = lane & 3;

    // ---- decode block -> (batch, level, tile). 256-voxel tiles. ----
    int bid = blockIdx.x;
    int b = bid / 1600;
    int tl = bid - b * 1600;
    int R, nbase, lt;
    if (tl < 16)       { R = 16; nbase = 0;      lt = tl;       }
    else if (tl < 144) { R = 32; nbase = 4096;   lt = tl - 16;  }
    else if (tl < 576) { R = 48; nbase = 36864;  lt = tl - 144; }
    else               { R = 64; nbase = 147456; lt = tl - 576; }
    const int td = R >> 3;
    const int tx = lt % td; const int t2 = lt / td;
    const int ty = t2 % td; const int tz = t2 / td;
    const int x0 = tx << 3, y0 = ty << 3, z0 = tz << 2;

    // ---- stage weights: coalesced float4 copy (1728 float4 = 14 strides) ----
    {
        const float4* src = (const float4*)d_ws;
        float4* dst = (float4*)ws;
        #pragma unroll
        for (int i = 0; i < 14; ++i) {
            int idx = t + i * 128;
            if (idx < 1728) dst[idx] = src[idx];
        }
    }

    // ---- stage halo: 600 rows x 16ch, permuted, j-rotated stores ----
    const float* inb = in + ((size_t)b * N_TOTAL + nbase) * 16;
    for (int row = t; row < 600; row += 128) {
        int hx = row % 10; int r2 = row / 10; int hy = r2 % 10; int hz = r2 / 10;
        int gx = x0 + hx - 1, gy = y0 + hy - 1, gz = z0 + hz - 1;
        float4 v0, v1, v2, v3;
        if ((unsigned)gx < (unsigned)R && (unsigned)gy < (unsigned)R && (unsigned)gz < (unsigned)R) {
            const float4* g = (const float4*)(inb + (size_t)((gz * R + gy) * R + gx) * 16);
            v0 = g[0]; v1 = g[1]; v2 = g[2]; v3 = g[3];
        } else {
            v0 = v1 = v2 = v3 = make_float4(0.f, 0.f, 0.f, 0.f);
        }
        float c[4][4] = {
            {v0.x, v1.x, v2.x, v3.x},
            {v0.y, v1.y, v2.y, v3.y},
            {v0.z, v1.z, v2.z, v3.z},
            {v0.w, v1.w, v2.w, v3.w},
        };
        float4* hrow = (float4*)(halo + row * 16);
        #pragma unroll
        for (int jj = 0; jj < 4; ++jj) {
            int j = (jj + row) & 3;
            hrow[j] = make_float4(cvt_tf32(c[j][0]), cvt_tf32(c[j][1]),
                                  cvt_tf32(c[j][2]), cvt_tf32(c[j][3]));
        }
    }
    __syncthreads();

    // ---- compute: warp wid = z-slab; register-cached 10-row window ----
    float acc[4][2][4];
    #pragma unroll
    for (int s = 0; s < 4; ++s)
        #pragma unroll
        for (int n = 0; n < 2; ++n)
            #pragma unroll
            for (int k = 0; k < 4; ++k) acc[s][n][k] = 0.f;

    const float4* hq = (const float4*)halo;   // row*4 + quad
    const float4* wq = (const float4*)ws;     // tap*64 + cout*4 + quad

    #pragma unroll 1
    for (int dx = 0; dx < 3; ++dx) {
        #pragma unroll 1
        for (int dz = 0; dz < 3; ++dz) {
            // rows ly = 0..9 at (hz = wid+dz, hx = r4+dx), quad c4
            const int rowbase = ((wid + dz) * 10) * 10 + (r4 + dx);
            float4 arow[10];
            #pragma unroll
            for (int j = 0; j < 10; ++j)
                arow[j] = hq[(rowbase + 10 * j) * 4 + c4];

            #pragma unroll
            for (int dy = 0; dy < 3; ++dy) {
                const int tap = (dz * 3 + dy) * 3 + dx;
                float4 bl = wq[tap * 64 + r4 * 4 + c4];
                float4 bh = wq[tap * 64 + (r4 + 8) * 4 + c4];
                #pragma unroll
                for (int s = 0; s < 4; ++s) {
                    float4 lo = arow[2 * s + dy];
                    float4 hi = arow[2 * s + dy + 1];
                    mma_tf32(acc[s][0], lo.x, hi.x, lo.y, hi.y, bl.x, bl.y);
                    mma_tf32(acc[s][1], lo.x, hi.x, lo.y, hi.y, bh.x, bh.y);
                    mma_tf32(acc[s][0], lo.z, hi.z, lo.w, hi.w, bl.z, bl.w);
                    mma_tf32(acc[s][1], lo.z, hi.z, lo.w, hi.w, bh.z, bh.w);
                }
            }
        }
    }

    // ---- epilogue: +bias, store ----
    const int n0 = 2 * c4;
    const float bl0 = bias[n0],     bl1 = bias[n0 + 1];
    const float bh0 = bias[8 + n0], bh1 = bias[8 + n0 + 1];

    const int gz = z0 + wid, gx = x0 + r4;
    #pragma unroll
    for (int s = 0; s < 4; ++s) {
        const int gy_lo = y0 + 2 * s, gy_hi = gy_lo + 1;
        float* olo = out + ((size_t)b * N_TOTAL + nbase +
                            (size_t)((gz * R + gy_lo) * R + gx)) * 16;
        float* ohi = out + ((size_t)b * N_TOTAL + nbase +
                            (size_t)((gz * R + gy_hi) * R + gx)) * 16;
        *(float2*)(olo + n0)     = make_float2(acc[s][0][0] + bl0, acc[s][0][1] + bl1);
        *(float2*)(olo + 8 + n0) = make_float2(acc[s][1][0] + bh0, acc[s][1][1] + bh1);
        *(float2*)(ohi + n0)     = make_float2(acc[s][0][2] + bl0, acc[s][0][3] + bl1);
        *(float2*)(ohi + 8 + n0) = make_float2(acc[s][1][2] + bh0, acc[s][1][3] + bh1);
    }
}

extern "C" void kernel_launch(void* const* d_in, const int* in_sizes, int n_in,
                              void* d_out, int out_size) {
    (void)in_sizes; (void)n_in; (void)out_size;
    const float* in  = (const float*)d_in[0];
    const float* w   = (const float*)d_in[1];
    const float* bs  = (const float*)d_in[2];
    float* out = (float*)d_out;

    weight_prep_kernel<<<27, 256>>>(w);

    cudaFuncSetAttribute(conv3d_mma_kernel,
                         cudaFuncAttributeMaxDynamicSharedMemorySize, (int)SMEM_BYTES);
    conv3d_mma_kernel<<<6400, 128, SMEM_BYTES>>>(in, bs, out);
}

// round 9
// speedup vs baseline: 3.3189x; 1.2588x over previous
#include <cuda_runtime.h>
#include <cstdint>

// Round 9: tf32 mma.sync implicit-GEMM, overhead-stripped.
//  - NO channel permutation: k-order redefined so A and B fragments are plain
//    unpermuted float4 loads (prep kernel writes B as [tap][cout][ch]).
//  - halo staged with cp.async (16B, zero-fill OOB): no cvt, no reg round-trip.
//    Activations enter the MMA as raw fp32 -> HW tf32 truncation (weights rna).
//  - B fragments read via __ldg from the 27KB L1-resident d_ws (no weight smem)
//    -> smem 38.4KB -> 5 blocks/SM.
// tile = 256 voxels (4z x 8y x 8x), 4 warps (one z-slab each).

constexpr int N_TOTAL = 409600;
constexpr int W_FLOATS = 27 * 16 * 16;   // [tap][cout][ch]

__device__ float d_ws[W_FLOATS];

__device__ __forceinline__ float cvt_tf32(float v) {
    uint32_t o; asm("cvt.rna.tf32.f32 %0, %1;" : "=r"(o) : "f"(v));
    return __uint_as_float(o);
}

__device__ __forceinline__ uint32_t smem_u32(const void* p) {
    uint32_t a;
    asm("{ .reg .u64 t; cvta.to.shared.u64 t, %1; cvt.u32.u64 %0, t; }" : "=r"(a) : "l"(p));
    return a;
}

__device__ __forceinline__ void mma_tf32(float c[4], float a0f, float a1f,
                                         float a2f, float a3f,
                                         float b0f, float b1f) {
    uint32_t a0 = __float_as_uint(a0f), a1 = __float_as_uint(a1f);
    uint32_t a2 = __float_as_uint(a2f), a3 = __float_as_uint(a3f);
    uint32_t b0 = __float_as_uint(b0f), b1 = __float_as_uint(b1f);
    asm volatile("mma.sync.aligned.m16n8k8.row.col.f32.tf32.tf32.f32 "
                 "{%0,%1,%2,%3}, {%4,%5,%6,%7}, {%8,%9}, {%0,%1,%2,%3};"
                 : "+f"(c[0]), "+f"(c[1]), "+f"(c[2]), "+f"(c[3])
                 : "r"(a0), "r"(a1), "r"(a2), "r"(a3), "r"(b0), "r"(b1));
}

// ---- prep: transpose + rna-round weights once: d_ws[tap][cout][ch] ----
__global__ void weight_prep_kernel(const float* __restrict__ wgt) {
    int i = blockIdx.x * 256 + threadIdx.x;
    if (i >= W_FLOATS) return;
    int tap = i >> 8;
    int rem = i & 255;
    int cout = rem >> 4, ch = rem & 15;
    d_ws[tap * 256 + cout * 16 + ch] = cvt_tf32(wgt[(cout * 16 + ch) * 27 + tap]);
}

__global__ __launch_bounds__(128, 5)
void conv3d_mma_kernel(const float* __restrict__ in,
                       const float* __restrict__ bias, float* __restrict__ out)
{
    __shared__ __align__(16) float halo[600 * 16];   // [row 600][ch 16], 38.4KB

    const int t = threadIdx.x;
    const int wid = t >> 5, lane = t & 31;
    const int r4 = lane >> 2, c4 = lane & 3;

    // ---- decode block -> (batch, level, tile). 256-voxel tiles. ----
    int bid = blockIdx.x;
    int b = bid / 1600;
    int tl = bid - b * 1600;
    int R, nbase, lt;
    if (tl < 16)       { R = 16; nbase = 0;      lt = tl;       }
    else if (tl < 144) { R = 32; nbase = 4096;   lt = tl - 16;  }
    else if (tl < 576) { R = 48; nbase = 36864;  lt = tl - 144; }
    else               { R = 64; nbase = 147456; lt = tl - 576; }
    const int td = R >> 3;
    const int tx = lt % td; const int t2 = lt / td;
    const int ty = t2 % td; const int tz = t2 / td;
    const int x0 = tx << 3, y0 = ty << 3, z0 = tz << 2;

    // ---- stage halo via cp.async: 600 rows x 4 comps, zero-fill OOB ----
    const float* inb = in + ((size_t)b * N_TOTAL + nbase) * 16;
    const uint32_t halo_base = smem_u32(halo);
    #pragma unroll
    for (int k = 0; k < 19; ++k) {
        int i = t + k * 128;
        if (i < 2400) {
            int comp = i & 3, row = i >> 2;
            int hx = row % 10; int r2 = row / 10; int hy = r2 % 10; int hz = r2 / 10;
            int gx = x0 + hx - 1, gy = y0 + hy - 1, gz = z0 + hz - 1;
            bool ok = (unsigned)gx < (unsigned)R && (unsigned)gy < (unsigned)R &&
                      (unsigned)gz < (unsigned)R;
            const float* src = ok ? inb + (size_t)((gz * R + gy) * R + gx) * 16 + comp * 4
                                  : inb;
            int sz = ok ? 16 : 0;
            uint32_t dst = halo_base + (uint32_t)(row * 16 + comp * 4) * 4u;
            asm volatile("cp.async.ca.shared.global [%0], [%1], 16, %2;"
                         :: "r"(dst), "l"(src), "r"(sz));
        }
    }
    asm volatile("cp.async.commit_group;");
    asm volatile("cp.async.wait_group 0;" ::: "memory");
    __syncthreads();

    // ---- compute: warp wid = z-slab; register-cached 10-row window ----
    float acc[4][2][4];
    #pragma unroll
    for (int s = 0; s < 4; ++s)
        #pragma unroll
        for (int n = 0; n < 2; ++n)
            #pragma unroll
            for (int k = 0; k < 4; ++k) acc[s][n][k] = 0.f;

    const float4* hq = (const float4*)halo;     // row*4 + c4
    const float4* wq = (const float4*)d_ws;     // tap*64 + cout*4 + c4

    #pragma unroll 1
    for (int dx = 0; dx < 3; ++dx) {
        #pragma unroll 1
        for (int dz = 0; dz < 3; ++dz) {
            const int rowbase = ((wid + dz) * 10) * 10 + (r4 + dx);
            float4 arow[10];
            #pragma unroll
            for (int j = 0; j < 10; ++j)
                arow[j] = hq[(rowbase + 10 * j) * 4 + c4];

            #pragma unroll
            for (int dy = 0; dy < 3; ++dy) {
                const int tap = (dz * 3 + dy) * 3 + dx;
                float4 bl = __ldg(&wq[tap * 64 + r4 * 4 + c4]);          // couts r4
                float4 bh = __ldg(&wq[tap * 64 + (r4 + 8) * 4 + c4]);    // couts r4+8
                #pragma unroll
                for (int s = 0; s < 4; ++s) {
                    float4 lo = arow[2 * s + dy];
                    float4 hi = arow[2 * s + dy + 1];
                    mma_tf32(acc[s][0], lo.x, hi.x, lo.y, hi.y, bl.x, bl.y);
                    mma_tf32(acc[s][1], lo.x, hi.x, lo.y, hi.y, bh.x, bh.y);
                    mma_tf32(acc[s][0], lo.z, hi.z, lo.w, hi.w, bl.z, bl.w);
                    mma_tf32(acc[s][1], lo.z, hi.z, lo.w, hi.w, bh.z, bh.w);
                }
            }
        }
    }

    // ---- epilogue: +bias, store ----
    const int n0 = 2 * c4;
    const float bl0 = bias[n0],     bl1 = bias[n0 + 1];
    const float bh0 = bias[8 + n0], bh1 = bias[8 + n0 + 1];

    const int gz = z0 + wid, gx = x0 + r4;
    #pragma unroll
    for (int s = 0; s < 4; ++s) {
        const int gy_lo = y0 + 2 * s, gy_hi = gy_lo + 1;
        float* olo = out + ((size_t)b * N_TOTAL + nbase +
                            (size_t)((gz * R + gy_lo) * R + gx)) * 16;
        float* ohi = out + ((size_t)b * N_TOTAL + nbase +
                            (size_t)((gz * R + gy_hi) * R + gx)) * 16;
        *(float2*)(olo + n0)     = make_float2(acc[s][0][0] + bl0, acc[s][0][1] + bl1);
        *(float2*)(olo + 8 + n0) = make_float2(acc[s][1][0] + bh0, acc[s][1][1] + bh1);
        *(float2*)(ohi + n0)     = make_float2(acc[s][0][2] + bl0, acc[s][0][3] + bl1);
        *(float2*)(ohi + 8 + n0) = make_float2(acc[s][1][2] + bh0, acc[s][1][3] + bh1);
    }
}

extern "C" void kernel_launch(void* const* d_in, const int* in_sizes, int n_in,
                              void* d_out, int out_size) {
    (void)in_sizes; (void)n_in; (void)out_size;
    const float* in  = (const float*)d_in[0];
    const float* w   = (const float*)d_in[1];
    const float* bs  = (const float*)d_in[2];
    float* out = (float*)d_out;

    weight_prep_kernel<<<27, 256>>>(w);
    conv3d_mma_kernel<<<6400, 128>>>(in, bs, out);
}

// round 10
// speedup vs baseline: 3.5456x; 1.0683x over previous
#include <cuda_runtime.h>
#include <cstdint>

// Round 10: R9 with operand-marshalling eliminated.
//  - A and B fragments flow as uint4 end-to-end (halo read as uint4, d_ws via
//    __ldg uint4); mma asm takes a/b as "r" with NO float<->uint casts.
//    R9 profile showed ~2000 unexplained slots/warp on fma/alu pipes = MOVs
//    from __float_as_uint marshalling around 432 mma calls.
//  - staging index math strength-reduced (incremental hx/hy/hz, no div/mod
//    in the loop; smem dst advances by constant).
// tile = 256 voxels (4z x 8y x 8x), 4 warps, 5 blocks/SM. Weights rna->tf32
// by prep kernel; activations raw fp32 (HW tf32 truncation in MMA).

constexpr int N_TOTAL = 409600;
constexpr int W_FLOATS = 27 * 16 * 16;   // [tap][cout][ch]

__device__ float d_ws[W_FLOATS];

__device__ __forceinline__ float cvt_tf32(float v) {
    uint32_t o; asm("cvt.rna.tf32.f32 %0, %1;" : "=r"(o) : "f"(v));
    return __uint_as_float(o);
}

__device__ __forceinline__ uint32_t smem_u32(const void* p) {
    uint32_t a;
    asm("{ .reg .u64 t; cvta.to.shared.u64 t, %1; cvt.u32.u64 %0, t; }" : "=r"(a) : "l"(p));
    return a;
}

// a/b are raw b32 (tf32) lanes, c/d are f32 — no cross-type moves generated.
__device__ __forceinline__ void mma_tf32(float c[4], uint32_t a0, uint32_t a1,
                                         uint32_t a2, uint32_t a3,
                                         uint32_t b0, uint32_t b1) {
    asm volatile("mma.sync.aligned.m16n8k8.row.col.f32.tf32.tf32.f32 "
                 "{%0,%1,%2,%3}, {%4,%5,%6,%7}, {%8,%9}, {%0,%1,%2,%3};"
                 : "+f"(c[0]), "+f"(c[1]), "+f"(c[2]), "+f"(c[3])
                 : "r"(a0), "r"(a1), "r"(a2), "r"(a3), "r"(b0), "r"(b1));
}

// ---- prep: transpose + rna-round weights once: d_ws[tap][cout][ch] ----
__global__ void weight_prep_kernel(const float* __restrict__ wgt) {
    int i = blockIdx.x * 256 + threadIdx.x;
    if (i >= W_FLOATS) return;
    int tap = i >> 8;
    int rem = i & 255;
    int cout = rem >> 4, ch = rem & 15;
    d_ws[tap * 256 + cout * 16 + ch] = cvt_tf32(wgt[(cout * 16 + ch) * 27 + tap]);
}

__global__ __launch_bounds__(128, 5)
void conv3d_mma_kernel(const float* __restrict__ in,
                       const float* __restrict__ bias, float* __restrict__ out)
{
    __shared__ __align__(16) uint32_t halo[600 * 16];   // [row 600][ch 16]

    const int t = threadIdx.x;
    const int wid = t >> 5, lane = t & 31;
    const int r4 = lane >> 2, c4 = lane & 3;

    // ---- decode block -> (batch, level, tile). 256-voxel tiles. ----
    int bid = blockIdx.x;
    int b = bid / 1600;
    int tl = bid - b * 1600;
    int R, nbase, lt;
    if (tl < 16)       { R = 16; nbase = 0;      lt = tl;       }
    else if (tl < 144) { R = 32; nbase = 4096;   lt = tl - 16;  }
    else if (tl < 576) { R = 48; nbase = 36864;  lt = tl - 144; }
    else               { R = 64; nbase = 147456; lt = tl - 576; }
    const int td = R >> 3;
    const int tx = lt % td; const int t2 = lt / td;
    const int ty = t2 % td; const int tz = t2 / td;
    const int x0 = tx << 3, y0 = ty << 3, z0 = tz << 2;

    // ---- stage halo via cp.async: incremental (hx,hy,hz), no div/mod ----
    const float* inb = in + ((size_t)b * N_TOTAL + nbase) * 16;
    {
        const int comp = t & 3;
        int row = t >> 2;                    // 0..31
        int hx = row % 10, hy = row / 10;    // one-time div
        int hz = 0;
        uint32_t dst = smem_u32(halo) + (uint32_t)(row * 16 + comp * 4) * 4u;
        const float* srcb = inb + comp * 4;
        int i = t;
        #pragma unroll
        for (int k = 0; k < 19; ++k) {
            if (i < 2400) {
                int gx = x0 + hx - 1, gy = y0 + hy - 1, gz = z0 + hz - 1;
                bool ok = (unsigned)gx < (unsigned)R && (unsigned)gy < (unsigned)R &&
                          (unsigned)gz < (unsigned)R;
                const float* src = ok ? srcb + (size_t)((gz * R + gy) * R + gx) * 16
                                      : inb;
                int sz = ok ? 16 : 0;
                asm volatile("cp.async.ca.shared.global [%0], [%1], 16, %2;"
                             :: "r"(dst), "l"(src), "r"(sz));
            }
            // advance 32 rows: 32 = 3*10 + 2
            hx += 2; hy += 3;
            if (hx >= 10) { hx -= 10; hy += 1; }
            if (hy >= 10) { hy -= 10; hz += 1; }
            dst += 32 * 16 * 4;
            i += 128;
        }
    }
    asm volatile("cp.async.commit_group;");
    asm volatile("cp.async.wait_group 0;" ::: "memory");
    __syncthreads();

    // ---- compute: warp wid = z-slab; register-cached 10-row window ----
    float acc[4][2][4];
    #pragma unroll
    for (int s = 0; s < 4; ++s)
        #pragma unroll
        for (int n = 0; n < 2; ++n)
            #pragma unroll
            for (int k = 0; k < 4; ++k) acc[s][n][k] = 0.f;

    const uint4* hq = (const uint4*)halo;     // row*4 + c4
    const uint4* wq = (const uint4*)d_ws;     // tap*64 + cout*4 + c4

    #pragma unroll 1
    for (int dx = 0; dx < 3; ++dx) {
        #pragma unroll 1
        for (int dz = 0; dz < 3; ++dz) {
            const int rowbase = ((wid + dz) * 10) * 10 + (r4 + dx);
            uint4 arow[10];
            #pragma unroll
            for (int j = 0; j < 10; ++j)
                arow[j] = hq[(rowbase + 10 * j) * 4 + c4];

            #pragma unroll
            for (int dy = 0; dy < 3; ++dy) {
                const int tap = (dz * 3 + dy) * 3 + dx;
                uint4 bl = __ldg(&wq[tap * 64 + r4 * 4 + c4]);          // couts r4
                uint4 bh = __ldg(&wq[tap * 64 + (r4 + 8) * 4 + c4]);    // couts r4+8
                #pragma unroll
                for (int s = 0; s < 4; ++s) {
                    uint4 lo = arow[2 * s + dy];
                    uint4 hi = arow[2 * s + dy + 1];
                    mma_tf32(acc[s][0], lo.x, hi.x, lo.y, hi.y, bl.x, bl.y);
                    mma_tf32(acc[s][1], lo.x, hi.x, lo.y, hi.y, bh.x, bh.y);
                    mma_tf32(acc[s][0], lo.z, hi.z, lo.w, hi.w, bl.z, bl.w);
                    mma_tf32(acc[s][1], lo.z, hi.z, lo.w, hi.w, bh.z, bh.w);
                }
            }
        }
    }

    // ---- epilogue: +bias, store ----
    const int n0 = 2 * c4;
    const float bl0 = bias[n0],     bl1 = bias[n0 + 1];
    const float bh0 = bias[8 + n0], bh1 = bias[8 + n0 + 1];

    const int gz = z0 + wid, gx = x0 + r4;
    #pragma unroll
    for (int s = 0; s < 4; ++s) {
        const int gy_lo = y0 + 2 * s, gy_hi = gy_lo + 1;
        float* olo = out + ((size_t)b * N_TOTAL + nbase +
                            (size_t)((gz * R + gy_lo) * R + gx)) * 16;
        float* ohi = out + ((size_t)b * N_TOTAL + nbase +
                            (size_t)((gz * R + gy_hi) * R + gx)) * 16;
        *(float2*)(olo + n0)     = make_float2(acc[s][0][0] + bl0, acc[s][0][1] + bl1);
        *(float2*)(olo + 8 + n0) = make_float2(acc[s][1][0] + bh0, acc[s][1][1] + bh1);
        *(float2*)(ohi + n0)     = make_float2(acc[s][0][2] + bl0, acc[s][0][3] + bl1);
        *(float2*)(ohi + 8 + n0) = make_float2(acc[s][1][2] + bh0, acc[s][1][3] + bh1);
    }
}

extern "C" void kernel_launch(void* const* d_in, const int* in_sizes, int n_in,
                              void* d_out, int out_size) {
    (void)in_sizes; (void)n_in; (void)out_size;
    const float* in  = (const float*)d_in[0];
    const float* w   = (const float*)d_in[1];
    const float* bs  = (const float*)d_in[2];
    float* out = (float*)d_out;

    weight_prep_kernel<<<27, 256>>>(w);
    conv3d_mma_kernel<<<6400, 128>>>(in, bs, out);
}

// round 11
// speedup vs baseline: 3.7758x; 1.0649x over previous
#include <cuda_runtime.h>
#include <cstdint>

// Round 11: R10 + full unroll of dz/dy (immediate addressing, load hoisting)
// and k-step-major MMA ordering (dependent accumulator updates spaced 8 MMAs
// apart instead of 1-2, covering HMMA latency at 5 warps/SMSP).
// tile = 256 voxels (4z x 8y x 8x), 4 warps, 5 blocks/SM.

constexpr int N_TOTAL = 409600;
constexpr int W_FLOATS = 27 * 16 * 16;   // [tap][cout][ch]

__device__ float d_ws[W_FLOATS];

__device__ __forceinline__ float cvt_tf32(float v) {
    uint32_t o; asm("cvt.rna.tf32.f32 %0, %1;" : "=r"(o) : "f"(v));
    return __uint_as_float(o);
}

__device__ __forceinline__ uint32_t smem_u32(const void* p) {
    uint32_t a;
    asm("{ .reg .u64 t; cvta.to.shared.u64 t, %1; cvt.u32.u64 %0, t; }" : "=r"(a) : "l"(p));
    return a;
}

__device__ __forceinline__ void mma_tf32(float c[4], uint32_t a0, uint32_t a1,
                                         uint32_t a2, uint32_t a3,
                                         uint32_t b0, uint32_t b1) {
    asm volatile("mma.sync.aligned.m16n8k8.row.col.f32.tf32.tf32.f32 "
                 "{%0,%1,%2,%3}, {%4,%5,%6,%7}, {%8,%9}, {%0,%1,%2,%3};"
                 : "+f"(c[0]), "+f"(c[1]), "+f"(c[2]), "+f"(c[3])
                 : "r"(a0), "r"(a1), "r"(a2), "r"(a3), "r"(b0), "r"(b1));
}

// ---- prep: transpose + rna-round weights once: d_ws[tap][cout][ch] ----
__global__ void weight_prep_kernel(const float* __restrict__ wgt) {
    int i = blockIdx.x * 256 + threadIdx.x;
    if (i >= W_FLOATS) return;
    int tap = i >> 8;
    int rem = i & 255;
    int cout = rem >> 4, ch = rem & 15;
    d_ws[tap * 256 + cout * 16 + ch] = cvt_tf32(wgt[(cout * 16 + ch) * 27 + tap]);
}

__global__ __launch_bounds__(128, 5)
void conv3d_mma_kernel(const float* __restrict__ in,
                       const float* __restrict__ bias, float* __restrict__ out)
{
    __shared__ __align__(16) uint32_t halo[600 * 16];   // [row 600][ch 16]

    const int t = threadIdx.x;
    const int wid = t >> 5, lane = t & 31;
    const int r4 = lane >> 2, c4 = lane & 3;

    // ---- decode block -> (batch, level, tile). 256-voxel tiles. ----
    int bid = blockIdx.x;
    int b = bid / 1600;
    int tl = bid - b * 1600;
    int R, nbase, lt;
    if (tl < 16)       { R = 16; nbase = 0;      lt = tl;       }
    else if (tl < 144) { R = 32; nbase = 4096;   lt = tl - 16;  }
    else if (tl < 576) { R = 48; nbase = 36864;  lt = tl - 144; }
    else               { R = 64; nbase = 147456; lt = tl - 576; }
    const int td = R >> 3;
    const int tx = lt % td; const int t2 = lt / td;
    const int ty = t2 % td; const int tz = t2 / td;
    const int x0 = tx << 3, y0 = ty << 3, z0 = tz << 2;

    // ---- stage halo via cp.async: incremental (hx,hy,hz), no div/mod ----
    const float* inb = in + ((size_t)b * N_TOTAL + nbase) * 16;
    {
        const int comp = t & 3;
        int row = t >> 2;                    // 0..31
        int hx = row % 10, hy = row / 10;    // one-time div
        int hz = 0;
        uint32_t dst = smem_u32(halo) + (uint32_t)(row * 16 + comp * 4) * 4u;
        const float* srcb = inb + comp * 4;
        int i = t;
        #pragma unroll
        for (int k = 0; k < 19; ++k) {
            if (i < 2400) {
                int gx = x0 + hx - 1, gy = y0 + hy - 1, gz = z0 + hz - 1;
                bool ok = (unsigned)gx < (unsigned)R && (unsigned)gy < (unsigned)R &&
                          (unsigned)gz < (unsigned)R;
                const float* src = ok ? srcb + (size_t)((gz * R + gy) * R + gx) * 16
                                      : inb;
                int sz = ok ? 16 : 0;
                asm volatile("cp.async.ca.shared.global [%0], [%1], 16, %2;"
                             :: "r"(dst), "l"(src), "r"(sz));
            }
            hx += 2; hy += 3;
            if (hx >= 10) { hx -= 10; hy += 1; }
            if (hy >= 10) { hy -= 10; hz += 1; }
            dst += 32 * 16 * 4;
            i += 128;
        }
    }
    asm volatile("cp.async.commit_group;");
    asm volatile("cp.async.wait_group 0;" ::: "memory");
    __syncthreads();

    // ---- compute ----
    float acc[4][2][4];
    #pragma unroll
    for (int s = 0; s < 4; ++s)
        #pragma unroll
        for (int n = 0; n < 2; ++n)
            #pragma unroll
            for (int k = 0; k < 4; ++k) acc[s][n][k] = 0.f;

    const uint4* hq = (const uint4*)halo + c4;                    // row*4
    const uint4* wq = (const uint4*)d_ws + r4 * 4 + c4;           // tap*64
    const int rb0 = (wid * 10) * 10 + r4;                         // dz=0, dx=0

    #pragma unroll 1
    for (int dx = 0; dx < 3; ++dx) {
        const uint4* hx0 = hq + (rb0 + dx) * 4;
        #pragma unroll
        for (int dz = 0; dz < 3; ++dz) {
            // 10-row window at (hz = wid+dz, hx = r4+dx) — immediate offsets
            uint4 arow[10];
            #pragma unroll
            for (int j = 0; j < 10; ++j)
                arow[j] = hx0[(dz * 100 + 10 * j) * 4];

            #pragma unroll
            for (int dy = 0; dy < 3; ++dy) {
                const int tap = (dz * 3 + dy) * 3 + dx;
                uint4 bl = __ldg(wq + tap * 64);          // couts r4
                uint4 bh = __ldg(wq + tap * 64 + 32);     // couts r4+8
                // k-step 0 for all 8 accumulators...
                #pragma unroll
                for (int s = 0; s < 4; ++s) {
                    uint4 lo = arow[2 * s + dy];
                    uint4 hi = arow[2 * s + dy + 1];
                    mma_tf32(acc[s][0], lo.x, hi.x, lo.y, hi.y, bl.x, bl.y);
                    mma_tf32(acc[s][1], lo.x, hi.x, lo.y, hi.y, bh.x, bh.y);
                }
                // ...then k-step 1 (dependent updates now 8 MMAs apart)
                #pragma unroll
                for (int s = 0; s < 4; ++s) {
                    uint4 lo = arow[2 * s + dy];
                    uint4 hi = arow[2 * s + dy + 1];
                    mma_tf32(acc[s][0], lo.z, hi.z, lo.w, hi.w, bl.z, bl.w);
                    mma_tf32(acc[s][1], lo.z, hi.z, lo.w, hi.w, bh.z, bh.w);
                }
            }
        }
    }

    // ---- epilogue: +bias, store ----
    const int n0 = 2 * c4;
    const float bl0 = bias[n0],     bl1 = bias[n0 + 1];
    const float bh0 = bias[8 + n0], bh1 = bias[8 + n0 + 1];

    const int gz = z0 + wid, gx = x0 + r4;
    #pragma unroll
    for (int s = 0; s < 4; ++s) {
        const int gy_lo = y0 + 2 * s, gy_hi = gy_lo + 1;
        float* olo = out + ((size_t)b * N_TOTAL + nbase +
                            (size_t)((gz * R + gy_lo) * R + gx)) * 16;
        float* ohi = out + ((size_t)b * N_TOTAL + nbase +
                            (size_t)((gz * R + gy_hi) * R + gx)) * 16;
        *(float2*)(olo + n0)     = make_float2(acc[s][0][0] + bl0, acc[s][0][1] + bl1);
        *(float2*)(olo + 8 + n0) = make_float2(acc[s][1][0] + bh0, acc[s][1][1] + bh1);
        *(float2*)(ohi + n0)     = make_float2(acc[s][0][2] + bl0, acc[s][0][3] + bl1);
        *(float2*)(ohi + 8 + n0) = make_float2(acc[s][1][2] + bh0, acc[s][1][3] + bh1);
    }
}

extern "C" void kernel_launch(void* const* d_in, const int* in_sizes, int n_in,
                              void* d_out, int out_size) {
    (void)in_sizes; (void)n_in; (void)out_size;
    const float* in  = (const float*)d_in[0];
    const float* w   = (const float*)d_in[1];
    const float* bs  = (const float*)d_in[2];
    float* out = (float*)d_out;

    weight_prep_kernel<<<27, 256>>>(w);
    conv3d_mma_kernel<<<6400, 128>>>(in, bs, out);
}